// round 5
// baseline (speedup 1.0000x reference)
#include <cuda_runtime.h>
#include <cuda_fp16.h>
#include <cstdint>
#include <math.h>

#define B_   4096
#define N_   32768
#define D_   1024
#define BM   128
#define BN   256
#define KC   64                  // K elems per chunk (64 fp16 = 128 B row)
#define NCH  (D_ / KC)           // 16
#define NBLK (N_ / BN)           // 128
#define BBLK (B_ / BM)           // 32

#define TILE_A  16384            // 128 rows x 128 B
#define TILE_BB 32768            // 256 rows x 128 B
#define STAGE_B (TILE_A + TILE_BB)   // 48 KB
#define SMEM_DYN (2 * STAGE_B)       // 96 KB double buffer

// ---------------- device-global scratch ------------------------------------
__device__ float   g_qinv[B_];
__device__ float   g_kinv[N_];
__device__ __half  g_qh[(size_t)B_ * D_];
__device__ __half  g_kh[(size_t)N_ * D_];
__device__ float4  g_topA[(size_t)B_ * NBLK];  // v0,i0,v1,i1
__device__ float2  g_topB[(size_t)B_ * NBLK];  // v2,i2
__device__ float2  g_ms  [(size_t)B_ * NBLK];  // sum,sumsq
__device__ float   g_var[B_];
__device__ int4    g_cand[B_];

// ---------------- helpers ---------------------------------------------------
__device__ __forceinline__ uint32_t smem_u32(const void* p) {
    uint32_t a;
    asm("{ .reg .u64 t; cvta.to.shared.u64 t, %1; cvt.u32.u64 %0, t; }" : "=r"(a) : "l"(p));
    return a;
}
__device__ __forceinline__ void ldsm4(uint32_t* r, uint32_t addr) {
    asm volatile("ldmatrix.sync.aligned.m8n8.x4.shared.b16 {%0,%1,%2,%3}, [%4];"
                 : "=r"(r[0]), "=r"(r[1]), "=r"(r[2]), "=r"(r[3]) : "r"(addr));
}
__device__ __forceinline__ void mma16816(float* c, const uint32_t* a, const uint32_t* b) {
    asm volatile("mma.sync.aligned.m16n8k16.row.col.f32.f16.f16.f32 "
                 "{%0,%1,%2,%3}, {%4,%5,%6,%7}, {%8,%9}, {%0,%1,%2,%3};"
                 : "+f"(c[0]), "+f"(c[1]), "+f"(c[2]), "+f"(c[3])
                 : "r"(a[0]), "r"(a[1]), "r"(a[2]), "r"(a[3]), "r"(b[0]), "r"(b[1]));
}
__device__ __forceinline__ void top3_ins(float v, int i,
                                         float& v0, int& i0, float& v1, int& i1,
                                         float& v2, int& i2) {
    if (v > v0)      { v2 = v1; i2 = i1; v1 = v0; i1 = i0; v0 = v; i0 = i; }
    else if (v > v1) { v2 = v1; i2 = i1; v1 = v;  i1 = i; }
    else if (v > v2) { v2 = v;  i2 = i; }
}

// ---------------------------------------------------------------------------
// Kernel 1a: query prep -> qinv + fp16(q_hat)
// ---------------------------------------------------------------------------
__global__ void prep_q_kernel(const float* __restrict__ x)
{
    const int row = blockIdx.x;
    const int tid = threadIdx.x;   // 256
    float4 v = reinterpret_cast<const float4*>(x + (size_t)row * D_)[tid];
    float s = v.x * v.x + v.y * v.y + v.z * v.z + v.w * v.w;
    __shared__ float sm[256];
    sm[tid] = s;
    __syncthreads();
    for (int o = 128; o > 0; o >>= 1) {
        if (tid < o) sm[tid] += sm[tid + o];
        __syncthreads();
    }
    const float inv = 1.0f / fmaxf(sqrtf(sm[0]), 1e-12f);
    if (tid == 0) g_qinv[row] = inv;

    __half2 h0 = __floats2half2_rn(v.x * inv, v.y * inv);
    __half2 h1 = __floats2half2_rn(v.z * inv, v.w * inv);
    uint2 pk;
    pk.x = *reinterpret_cast<uint32_t*>(&h0);
    pk.y = *reinterpret_cast<uint32_t*>(&h1);
    reinterpret_cast<uint2*>(g_qh + (size_t)row * D_)[tid] = pk;
}

// ---------------------------------------------------------------------------
// Kernel 1b: key prep -> kinv + fp16(k_hat)
// ---------------------------------------------------------------------------
__global__ void prep_k_kernel(const float* __restrict__ x)
{
    const int row = blockIdx.x;
    const int tid = threadIdx.x;
    float4 v = reinterpret_cast<const float4*>(x + (size_t)row * D_)[tid];
    float s = v.x * v.x + v.y * v.y + v.z * v.z + v.w * v.w;
    __shared__ float sm[256];
    sm[tid] = s;
    __syncthreads();
    for (int o = 128; o > 0; o >>= 1) {
        if (tid < o) sm[tid] += sm[tid + o];
        __syncthreads();
    }
    const float inv = 1.0f / fmaxf(sqrtf(sm[0]), 1e-12f);
    if (tid == 0) g_kinv[row] = inv;

    __half2 h0 = __floats2half2_rn(v.x * inv, v.y * inv);
    __half2 h1 = __floats2half2_rn(v.z * inv, v.w * inv);
    uint2 pk;
    pk.x = *reinterpret_cast<uint32_t*>(&h0);
    pk.y = *reinterpret_cast<uint32_t*>(&h1);
    reinterpret_cast<uint2*>(g_kh + (size_t)row * D_)[tid] = pk;
}

// ---------------------------------------------------------------------------
// Kernel 2: mma.sync fp16 GEMM, 128x256 CTA tile, 8 warps @ 64x64
//           + fused top3/sum/sumsq
// ---------------------------------------------------------------------------
__global__ __launch_bounds__(256, 1)
void sim_kernel()
{
    extern __shared__ char dynsmem[];
    const uint32_t sbase = smem_u32(dynsmem);

    const int tid = threadIdx.x;
    const int l   = tid & 31;
    const int wid = tid >> 5;
    const int wm  = wid >> 2;      // 0..1  -> 64-row half
    const int wn  = wid & 3;       // 0..3  -> 64-col slice
    const int nblk = blockIdx.x;
    const int bblk = blockIdx.y;

    const char* srcA = (const char*)(g_qh + (size_t)bblk * BM * D_);
    const char* srcB = (const char*)(g_kh + (size_t)nblk * BN * D_);

    // ---- async tile loader (48 KB per chunk) ------------------------------
    auto load_chunk = [&](int c, int st) {
        const uint32_t stb = sbase + st * STAGE_B;
        // A: i = 0..3 -> 1024 x 16B ; B: i = 4..11 -> 2048 x 16B
#pragma unroll
        for (int i = 0; i < 4; i++) {
            const int o = i * 256 + tid;
            const int r = o >> 3;
            const int j = o & 7;
            const char* g = srcA + (size_t)r * (D_ * 2) + c * 128 + j * 16;
            uint32_t off = (uint32_t)(r * 128 + j * 16);
            uint32_t dst = stb + (off ^ ((off >> 3) & 0x70));
            asm volatile("cp.async.cg.shared.global [%0], [%1], 16;" :: "r"(dst), "l"(g));
        }
#pragma unroll
        for (int i = 0; i < 8; i++) {
            const int o = i * 256 + tid;
            const int r = o >> 3;
            const int j = o & 7;
            const char* g = srcB + (size_t)r * (D_ * 2) + c * 128 + j * 16;
            uint32_t off = (uint32_t)(r * 128 + j * 16);
            uint32_t dst = stb + TILE_A + (off ^ ((off >> 3) & 0x70));
            asm volatile("cp.async.cg.shared.global [%0], [%1], 16;" :: "r"(dst), "l"(g));
        }
        asm volatile("cp.async.commit_group;" ::: "memory");
    };

    // ---- per-lane ldmatrix offsets ----------------------------------------
    const uint32_t rowA = l & 15;
    const uint32_t acs  = (l >> 4) * 16;
    const uint32_t xa   = (rowA & 7) << 4;
    const uint32_t aoff = rowA * 128 + (uint32_t)wm * 8192;    // wm*64 rows

    const uint32_t rowB = (l & 7) + ((l >> 4) << 3);
    const uint32_t bcs  = ((l >> 3) & 1) * 16;
    const uint32_t xb   = (rowB & 7) << 4;
    const uint32_t boff = rowB * 128 + (uint32_t)wn * 8192;    // wn*64 rows

    float acc[4][8][4];
#pragma unroll
    for (int m = 0; m < 4; m++)
#pragma unroll
        for (int n = 0; n < 8; n++)
#pragma unroll
            for (int e = 0; e < 4; e++) acc[m][n][e] = 0.f;

    load_chunk(0, 0);

    for (int c = 0; c < NCH; c++) {
        const int st = c & 1;
        if (c + 1 < NCH) {
            load_chunk(c + 1, st ^ 1);
            asm volatile("cp.async.wait_group 1;" ::: "memory");
        } else {
            asm volatile("cp.async.wait_group 0;" ::: "memory");
        }
        __syncthreads();

        const uint32_t TBa = sbase + st * STAGE_B + aoff;
        const uint32_t TBb = sbase + st * STAGE_B + TILE_A + boff;

#pragma unroll
        for (int ks = 0; ks < 4; ks++) {
            const uint32_t ka = (32u * ks + acs) ^ xa;
            const uint32_t kb = (32u * ks + bcs) ^ xb;
            uint32_t af[4][4];
#pragma unroll
            for (int m = 0; m < 4; m++) ldsm4(af[m], TBa + m * 2048 + ka);

            uint32_t bf[8][2];
#pragma unroll
            for (int p = 0; p < 4; p++) {
                uint32_t t4[4];
                ldsm4(t4, TBb + p * 2048 + kb);
                bf[2 * p][0] = t4[0]; bf[2 * p][1] = t4[1];
                bf[2 * p + 1][0] = t4[2]; bf[2 * p + 1][1] = t4[3];
            }
#pragma unroll
            for (int m = 0; m < 4; m++)
#pragma unroll
                for (int n = 0; n < 8; n++) mma16816(acc[m][n], af[m], bf[n]);
        }
        __syncthreads();
    }

    // ---- epilogue: per-row sum/sumsq/top3 ---------------------------------
    float* spart = reinterpret_cast<float*>(dynsmem);   // 128 rows x 4 warps x 8 f

#pragma unroll
    for (int m = 0; m < 4; m++) {
#pragma unroll
        for (int h = 0; h < 2; h++) {
            float sum = 0.f, sq = 0.f;
            float v0 = -2.f, v1 = -2.f, v2 = -2.f;
            int   i0 = 0, i1 = 0, i2 = 0;
            const int colbase = nblk * BN + wn * 64 + 2 * (l & 3);
#pragma unroll
            for (int n = 0; n < 8; n++) {
#pragma unroll
                for (int e = 0; e < 2; e++) {
                    const float v = acc[m][n][2 * h + e];
                    sum += v;
                    sq = fmaf(v, v, sq);
                    top3_ins(v, colbase + 8 * n + e, v0, i0, v1, i1, v2, i2);
                }
            }
#pragma unroll
            for (int o = 1; o <= 2; o <<= 1) {
                float ov0 = __shfl_xor_sync(0xffffffffu, v0, o);
                float ov1 = __shfl_xor_sync(0xffffffffu, v1, o);
                float ov2 = __shfl_xor_sync(0xffffffffu, v2, o);
                int   oi0 = __shfl_xor_sync(0xffffffffu, i0, o);
                int   oi1 = __shfl_xor_sync(0xffffffffu, i1, o);
                int   oi2 = __shfl_xor_sync(0xffffffffu, i2, o);
                sum += __shfl_xor_sync(0xffffffffu, sum, o);
                sq  += __shfl_xor_sync(0xffffffffu, sq, o);
                top3_ins(ov0, oi0, v0, i0, v1, i1, v2, i2);
                top3_ins(ov1, oi1, v0, i0, v1, i1, v2, i2);
                top3_ins(ov2, oi2, v0, i0, v1, i1, v2, i2);
            }
            if ((l & 3) == 0) {
                const int rloc = wm * 64 + 16 * m + (l >> 2) + 8 * h;
                float* p = spart + (rloc * 4 + wn) * 8;
                p[0] = sum; p[1] = sq;
                p[2] = v0;  p[3] = v1;  p[4] = v2;
                p[5] = __int_as_float(i0);
                p[6] = __int_as_float(i1);
                p[7] = __int_as_float(i2);
            }
        }
    }
    __syncthreads();

    if (tid < 128) {
        float sum = 0.f, sq = 0.f;
        float v0 = -2.f, v1 = -2.f, v2 = -2.f;
        int   i0 = 0, i1 = 0, i2 = 0;
#pragma unroll
        for (int w = 0; w < 4; w++) {
            const float* p = spart + (tid * 4 + w) * 8;
            sum += p[0]; sq += p[1];
            top3_ins(p[2], __float_as_int(p[5]), v0, i0, v1, i1, v2, i2);
            top3_ins(p[3], __float_as_int(p[6]), v0, i0, v1, i1, v2, i2);
            top3_ins(p[4], __float_as_int(p[7]), v0, i0, v1, i1, v2, i2);
        }
        const int gr = bblk * BM + tid;
        const size_t o = (size_t)gr * NBLK + nblk;
        g_ms[o]   = make_float2(sum, sq);
        g_topA[o] = make_float4(v0, __int_as_float(i0), v1, __int_as_float(i1));
        g_topB[o] = make_float2(v2, __int_as_float(i2));
    }
}

// ---------------------------------------------------------------------------
// Kernel 3: reduce 128 block-partials per row -> variance + global top-3
// ---------------------------------------------------------------------------
__global__ void finalize_kernel()
{
    const int row = blockIdx.x;
    const int tid = threadIdx.x;   // 128 == NBLK

    __shared__ float4 sA[128];
    __shared__ float2 sB[128];
    __shared__ float2 sM[128];
    const size_t o = (size_t)row * NBLK + tid;
    sA[tid] = g_topA[o];
    sB[tid] = g_topB[o];
    sM[tid] = g_ms[o];
    __syncthreads();

    for (int off = 64; off > 0; off >>= 1) {
        if (tid < off) {
            float4 a = sA[tid]; float2 a2 = sB[tid];
            float4 b = sA[tid + off]; float2 b2 = sB[tid + off];
            float v0 = a.x, v1 = a.z, v2 = a2.x;
            int   i0 = __float_as_int(a.y), i1 = __float_as_int(a.w),
                  i2 = __float_as_int(a2.y);
            top3_ins(b.x,  __float_as_int(b.y),  v0, i0, v1, i1, v2, i2);
            top3_ins(b.z,  __float_as_int(b.w),  v0, i0, v1, i1, v2, i2);
            top3_ins(b2.x, __float_as_int(b2.y), v0, i0, v1, i1, v2, i2);
            sA[tid] = make_float4(v0, __int_as_float(i0), v1, __int_as_float(i1));
            sB[tid] = make_float2(v2, __int_as_float(i2));
            float2 x = sM[tid], y = sM[tid + off];
            sM[tid] = make_float2(x.x + y.x, x.y + y.y);
        }
        __syncthreads();
    }
    if (tid == 0) {
        const float s = sM[0].x, q2 = sM[0].y;
        g_var[row] = (q2 - s * s / (float)N_) / (float)(N_ - 1);
        g_cand[row] = make_int4(__float_as_int(sA[0].y), __float_as_int(sA[0].w),
                                __float_as_int(sB[0].y), 0);
    }
}

// ---------------------------------------------------------------------------
// Kernel 4: exact fp32 rescore of 3 candidates + gather values[best]
// ---------------------------------------------------------------------------
__global__ void rescore_kernel(const float* __restrict__ Q, const float* __restrict__ K,
                               const float* __restrict__ V, float* __restrict__ out)
{
    const int row = blockIdx.x;
    const int tid = threadIdx.x;   // 256
    const int4 cd = g_cand[row];
    const float qi = g_qinv[row];

    float4 q = reinterpret_cast<const float4*>(Q + (size_t)row * D_)[tid];
    q.x *= qi; q.y *= qi; q.z *= qi; q.w *= qi;

    __shared__ float r[3][256];
    __shared__ int sbest;
    const int cands[3] = {cd.x, cd.y, cd.z};
#pragma unroll
    for (int c = 0; c < 3; c++) {
        const float ki = g_kinv[cands[c]];
        float4 k = reinterpret_cast<const float4*>(K + (size_t)cands[c] * D_)[tid];
        r[c][tid] = (q.x * k.x + q.y * k.y + q.z * k.z + q.w * k.w) * ki;
    }
    __syncthreads();
    for (int off = 128; off > 0; off >>= 1) {
        if (tid < off) {
            r[0][tid] += r[0][tid + off];
            r[1][tid] += r[1][tid + off];
            r[2][tid] += r[2][tid + off];
        }
        __syncthreads();
    }
    if (tid == 0) {
        float bv = r[0][0]; int bi = cands[0];
        for (int c = 1; c < 3; c++) {
            const float v = r[c][0];
            if (v > bv || (v == bv && cands[c] < bi)) { bv = v; bi = cands[c]; }
        }
        sbest = bi;
    }
    __syncthreads();
    reinterpret_cast<float4*>(out + (size_t)row * D_)[tid] =
        reinterpret_cast<const float4*>(V + (size_t)sbest * D_)[tid];
}

// ---------------------------------------------------------------------------
// Kernel 5: deterministic mean of row variances -> out[B*D]
// ---------------------------------------------------------------------------
__global__ void var_mean_kernel(float* __restrict__ out)
{
    __shared__ float sm[1024];
    const int tid = threadIdx.x;
    sm[tid] = g_var[tid] + g_var[tid + 1024] + g_var[tid + 2048] + g_var[tid + 3072];
    __syncthreads();
    for (int o = 512; o > 0; o >>= 1) {
        if (tid < o) sm[tid] += sm[tid + o];
        __syncthreads();
    }
    if (tid == 0) out[(size_t)B_ * D_] = sm[0] / (float)B_;
}

// ---------------------------------------------------------------------------
extern "C" void kernel_launch(void* const* d_in, const int* in_sizes, int n_in,
                              void* d_out, int out_size)
{
    const float* query  = (const float*)d_in[0];
    const float* keys   = (const float*)d_in[1];
    const float* values = (const float*)d_in[2];
    float* out = (float*)d_out;

    cudaFuncSetAttribute(sim_kernel, cudaFuncAttributeMaxDynamicSharedMemorySize, SMEM_DYN);

    prep_q_kernel<<<B_, 256>>>(query);
    prep_k_kernel<<<N_, 256>>>(keys);

    sim_kernel<<<dim3(NBLK, BBLK), 256, SMEM_DYN>>>();

    finalize_kernel<<<B_, 128>>>();
    rescore_kernel<<<B_, 256>>>(query, keys, values, out);
    var_mean_kernel<<<1, 1024>>>(out);
}

// round 6
// speedup vs baseline: 1.2052x; 1.2052x over previous
#include <cuda_runtime.h>
#include <cuda_fp16.h>
#include <cstdint>
#include <math.h>

#define B_   4096
#define N_   32768
#define D_   1024
#define BM   128
#define BN   128
#define KC   64                  // K elems per chunk (64 fp16 = 128 B row)
#define NCH  (D_ / KC)           // 16
#define NBLK (N_ / BN)           // 256
#define BBLK (B_ / BM)           // 32

#define TILE_B  16384            // 128 rows x 128 B
#define STAGE_B (2 * TILE_B)     // A(q), B(k) = 32 KB
#define NSTAGE  3
#define SMEM_DYN (NSTAGE * STAGE_B)   // 96 KB triple buffer

// ---------------- device-global scratch ------------------------------------
__device__ float   g_qinv[B_];
__device__ float   g_kinv[N_];
__device__ __half  g_qh[(size_t)B_ * D_];
__device__ __half  g_kh[(size_t)N_ * D_];
__device__ float4  g_topA[(size_t)B_ * NBLK];  // v0,i0,v1,i1
__device__ float2  g_topB[(size_t)B_ * NBLK];  // v2,i2
__device__ float2  g_ms  [(size_t)B_ * NBLK];  // sum,sumsq
__device__ float   g_var[B_];
__device__ int4    g_cand[B_];

// ---------------- helpers ---------------------------------------------------
__device__ __forceinline__ uint32_t smem_u32(const void* p) {
    uint32_t a;
    asm("{ .reg .u64 t; cvta.to.shared.u64 t, %1; cvt.u32.u64 %0, t; }" : "=r"(a) : "l"(p));
    return a;
}
__device__ __forceinline__ void ldsm4(uint32_t* r, uint32_t addr) {
    asm volatile("ldmatrix.sync.aligned.m8n8.x4.shared.b16 {%0,%1,%2,%3}, [%4];"
                 : "=r"(r[0]), "=r"(r[1]), "=r"(r[2]), "=r"(r[3]) : "r"(addr));
}
__device__ __forceinline__ void mma16816(float* c, const uint32_t* a, const uint32_t* b) {
    asm volatile("mma.sync.aligned.m16n8k16.row.col.f32.f16.f16.f32 "
                 "{%0,%1,%2,%3}, {%4,%5,%6,%7}, {%8,%9}, {%0,%1,%2,%3};"
                 : "+f"(c[0]), "+f"(c[1]), "+f"(c[2]), "+f"(c[3])
                 : "r"(a[0]), "r"(a[1]), "r"(a[2]), "r"(a[3]), "r"(b[0]), "r"(b[1]));
}
__device__ __forceinline__ void top3_ins(float v, int i,
                                         float& v0, int& i0, float& v1, int& i1,
                                         float& v2, int& i2) {
    if (v > v0)      { v2 = v1; i2 = i1; v1 = v0; i1 = i0; v0 = v; i0 = i; }
    else if (v > v1) { v2 = v1; i2 = i1; v1 = v;  i1 = i; }
    else if (v > v2) { v2 = v;  i2 = i; }
}

// ---------------------------------------------------------------------------
// Kernel 1a: query prep -> qinv + fp16(q_hat)
// ---------------------------------------------------------------------------
__global__ void prep_q_kernel(const float* __restrict__ x)
{
    const int row = blockIdx.x;
    const int tid = threadIdx.x;   // 256
    float4 v = reinterpret_cast<const float4*>(x + (size_t)row * D_)[tid];
    float s = v.x * v.x + v.y * v.y + v.z * v.z + v.w * v.w;
    __shared__ float sm[256];
    sm[tid] = s;
    __syncthreads();
    for (int o = 128; o > 0; o >>= 1) {
        if (tid < o) sm[tid] += sm[tid + o];
        __syncthreads();
    }
    const float inv = 1.0f / fmaxf(sqrtf(sm[0]), 1e-12f);
    if (tid == 0) g_qinv[row] = inv;

    __half2 h0 = __floats2half2_rn(v.x * inv, v.y * inv);
    __half2 h1 = __floats2half2_rn(v.z * inv, v.w * inv);
    uint2 pk;
    pk.x = *reinterpret_cast<uint32_t*>(&h0);
    pk.y = *reinterpret_cast<uint32_t*>(&h1);
    reinterpret_cast<uint2*>(g_qh + (size_t)row * D_)[tid] = pk;
}

// ---------------------------------------------------------------------------
// Kernel 1b: key prep -> kinv + fp16(k_hat)
// ---------------------------------------------------------------------------
__global__ void prep_k_kernel(const float* __restrict__ x)
{
    const int row = blockIdx.x;
    const int tid = threadIdx.x;
    float4 v = reinterpret_cast<const float4*>(x + (size_t)row * D_)[tid];
    float s = v.x * v.x + v.y * v.y + v.z * v.z + v.w * v.w;
    __shared__ float sm[256];
    sm[tid] = s;
    __syncthreads();
    for (int o = 128; o > 0; o >>= 1) {
        if (tid < o) sm[tid] += sm[tid + o];
        __syncthreads();
    }
    const float inv = 1.0f / fmaxf(sqrtf(sm[0]), 1e-12f);
    if (tid == 0) g_kinv[row] = inv;

    __half2 h0 = __floats2half2_rn(v.x * inv, v.y * inv);
    __half2 h1 = __floats2half2_rn(v.z * inv, v.w * inv);
    uint2 pk;
    pk.x = *reinterpret_cast<uint32_t*>(&h0);
    pk.y = *reinterpret_cast<uint32_t*>(&h1);
    reinterpret_cast<uint2*>(g_kh + (size_t)row * D_)[tid] = pk;
}

// ---------------------------------------------------------------------------
// Kernel 2: mma.sync fp16 GEMM (128x128 tile, 2 CTAs/SM, 3-stage pipeline)
//           + fused top3/sum/sumsq
// ---------------------------------------------------------------------------
__global__ __launch_bounds__(256, 2)
void sim_kernel()
{
    extern __shared__ char dynsmem[];
    const uint32_t sbase = smem_u32(dynsmem);

    const int tid = threadIdx.x;
    const int l   = tid & 31;
    const int wid = tid >> 5;
    const int wm  = wid >> 2;      // 0..1
    const int wn  = wid & 3;       // 0..3
    const int nblk = blockIdx.x;
    const int bblk = blockIdx.y;

    const char* srcA = (const char*)(g_qh + (size_t)bblk * BM * D_);
    const char* srcB = (const char*)(g_kh + (size_t)nblk * BN * D_);

    // ---- async tile loader (32 KB per chunk) ------------------------------
    auto load_chunk = [&](int c, int st) {
        const uint32_t stb = sbase + st * STAGE_B;
        const char* srcs[2] = {srcA, srcB};
#pragma unroll
        for (int i = 0; i < 8; i++) {
            const int t = i >> 2;
            const int w = (i & 3) * 256 + tid;
            const int r = w >> 3;
            const int j = w & 7;
            const char* g = srcs[t] + (size_t)r * (D_ * 2) + c * 128 + j * 16;
            uint32_t off = (uint32_t)(r * 128 + j * 16);
            uint32_t dst = stb + t * TILE_B + (off ^ ((off >> 3) & 0x70));
            asm volatile("cp.async.cg.shared.global [%0], [%1], 16;" :: "r"(dst), "l"(g));
        }
        asm volatile("cp.async.commit_group;" ::: "memory");
    };

    // ---- per-lane ldmatrix offsets ----------------------------------------
    const uint32_t rowA = l & 15;
    const uint32_t acs  = (l >> 4) * 16;
    const uint32_t xa   = (rowA & 7) << 4;
    const uint32_t aoff = rowA * 128 + (uint32_t)wm * 8192;   // wm*64 rows

    const uint32_t rowB = (l & 7) + ((l >> 4) << 3);
    const uint32_t bcs  = ((l >> 3) & 1) * 16;
    const uint32_t xb   = (rowB & 7) << 4;
    const uint32_t boff = rowB * 128 + (uint32_t)wn * 4096;   // wn*32 rows

    float acc[4][4][4];
#pragma unroll
    for (int m = 0; m < 4; m++)
#pragma unroll
        for (int n = 0; n < 4; n++)
#pragma unroll
            for (int e = 0; e < 4; e++) acc[m][n][e] = 0.f;

    // prime 2 stages
    load_chunk(0, 0);
    load_chunk(1, 1);

    for (int c = 0; c < NCH; c++) {
        const int st = c % NSTAGE;
        if (c + 1 < NCH) {
            asm volatile("cp.async.wait_group 1;" ::: "memory");
        } else {
            asm volatile("cp.async.wait_group 0;" ::: "memory");
        }
        // barrier doubles as: (a) chunk-c data visible to all warps,
        // (b) all warps finished compute on chunk c-1, so its stage
        //     ((c+2) % NSTAGE) may be overwritten by the load below.
        __syncthreads();
        if (c + 2 < NCH) load_chunk(c + 2, (c + 2) % NSTAGE);

        const uint32_t TBa = sbase + st * STAGE_B + aoff;
        const uint32_t TBb = sbase + st * STAGE_B + TILE_B + boff;

#pragma unroll
        for (int ks = 0; ks < 4; ks++) {
            const uint32_t ka = (32u * ks + acs) ^ xa;
            const uint32_t kb = (32u * ks + bcs) ^ xb;
            uint32_t af[4][4];
#pragma unroll
            for (int m = 0; m < 4; m++) ldsm4(af[m], TBa + m * 2048 + ka);

            uint32_t bf[4][2];
#pragma unroll
            for (int p = 0; p < 2; p++) {
                uint32_t t4[4];
                ldsm4(t4, TBb + p * 2048 + kb);
                bf[2 * p][0] = t4[0]; bf[2 * p][1] = t4[1];
                bf[2 * p + 1][0] = t4[2]; bf[2 * p + 1][1] = t4[3];
            }
#pragma unroll
            for (int m = 0; m < 4; m++)
#pragma unroll
                for (int n = 0; n < 4; n++) mma16816(acc[m][n], af[m], bf[n]);
        }
    }
    __syncthreads();   // compute done before epilogue reuses smem

    // ---- epilogue: per-row sum/sumsq/top3 ---------------------------------
    float* spart = reinterpret_cast<float*>(dynsmem);   // 128 rows x 4 nwarps x 8 f

#pragma unroll
    for (int m = 0; m < 4; m++) {
#pragma unroll
        for (int h = 0; h < 2; h++) {
            float sum = 0.f, sq = 0.f;
            float v0 = -2.f, v1 = -2.f, v2 = -2.f;
            int   i0 = 0, i1 = 0, i2 = 0;
            const int colbase = nblk * BN + wn * 32 + 2 * (l & 3);
#pragma unroll
            for (int n = 0; n < 4; n++) {
#pragma unroll
                for (int e = 0; e < 2; e++) {
                    const float v = acc[m][n][2 * h + e];
                    sum += v;
                    sq = fmaf(v, v, sq);
                    top3_ins(v, colbase + 8 * n + e, v0, i0, v1, i1, v2, i2);
                }
            }
#pragma unroll
            for (int o = 1; o <= 2; o <<= 1) {
                float ov0 = __shfl_xor_sync(0xffffffffu, v0, o);
                float ov1 = __shfl_xor_sync(0xffffffffu, v1, o);
                float ov2 = __shfl_xor_sync(0xffffffffu, v2, o);
                int   oi0 = __shfl_xor_sync(0xffffffffu, i0, o);
                int   oi1 = __shfl_xor_sync(0xffffffffu, i1, o);
                int   oi2 = __shfl_xor_sync(0xffffffffu, i2, o);
                sum += __shfl_xor_sync(0xffffffffu, sum, o);
                sq  += __shfl_xor_sync(0xffffffffu, sq, o);
                top3_ins(ov0, oi0, v0, i0, v1, i1, v2, i2);
                top3_ins(ov1, oi1, v0, i0, v1, i1, v2, i2);
                top3_ins(ov2, oi2, v0, i0, v1, i1, v2, i2);
            }
            if ((l & 3) == 0) {
                const int rloc = wm * 64 + 16 * m + (l >> 2) + 8 * h;
                float* p = spart + (rloc * 4 + wn) * 8;
                p[0] = sum; p[1] = sq;
                p[2] = v0;  p[3] = v1;  p[4] = v2;
                p[5] = __int_as_float(i0);
                p[6] = __int_as_float(i1);
                p[7] = __int_as_float(i2);
            }
        }
    }
    __syncthreads();

    if (tid < 128) {
        float sum = 0.f, sq = 0.f;
        float v0 = -2.f, v1 = -2.f, v2 = -2.f;
        int   i0 = 0, i1 = 0, i2 = 0;
#pragma unroll
        for (int w = 0; w < 4; w++) {
            const float* p = spart + (tid * 4 + w) * 8;
            sum += p[0]; sq += p[1];
            top3_ins(p[2], __float_as_int(p[5]), v0, i0, v1, i1, v2, i2);
            top3_ins(p[3], __float_as_int(p[6]), v0, i0, v1, i1, v2, i2);
            top3_ins(p[4], __float_as_int(p[7]), v0, i0, v1, i1, v2, i2);
        }
        const int gr = bblk * BM + tid;
        const size_t o = (size_t)gr * NBLK + nblk;
        g_ms[o]   = make_float2(sum, sq);
        g_topA[o] = make_float4(v0, __int_as_float(i0), v1, __int_as_float(i1));
        g_topB[o] = make_float2(v2, __int_as_float(i2));
    }
}

// ---------------------------------------------------------------------------
// Kernel 3: reduce 256 block-partials per row -> variance + global top-3
// ---------------------------------------------------------------------------
__global__ void finalize_kernel()
{
    const int row = blockIdx.x;
    const int tid = threadIdx.x;   // 256 == NBLK

    __shared__ float4 sA[256];
    __shared__ float2 sB[256];
    __shared__ float2 sM[256];
    const size_t o = (size_t)row * NBLK + tid;
    sA[tid] = g_topA[o];
    sB[tid] = g_topB[o];
    sM[tid] = g_ms[o];
    __syncthreads();

    for (int off = 128; off > 0; off >>= 1) {
        if (tid < off) {
            float4 a = sA[tid]; float2 a2 = sB[tid];
            float4 b = sA[tid + off]; float2 b2 = sB[tid + off];
            float v0 = a.x, v1 = a.z, v2 = a2.x;
            int   i0 = __float_as_int(a.y), i1 = __float_as_int(a.w),
                  i2 = __float_as_int(a2.y);
            top3_ins(b.x,  __float_as_int(b.y),  v0, i0, v1, i1, v2, i2);
            top3_ins(b.z,  __float_as_int(b.w),  v0, i0, v1, i1, v2, i2);
            top3_ins(b2.x, __float_as_int(b2.y), v0, i0, v1, i1, v2, i2);
            sA[tid] = make_float4(v0, __int_as_float(i0), v1, __int_as_float(i1));
            sB[tid] = make_float2(v2, __int_as_float(i2));
            float2 x = sM[tid], y = sM[tid + off];
            sM[tid] = make_float2(x.x + y.x, x.y + y.y);
        }
        __syncthreads();
    }
    if (tid == 0) {
        const float s = sM[0].x, q2 = sM[0].y;
        g_var[row] = (q2 - s * s / (float)N_) / (float)(N_ - 1);
        g_cand[row] = make_int4(__float_as_int(sA[0].y), __float_as_int(sA[0].w),
                                __float_as_int(sB[0].y), 0);
    }
}

// ---------------------------------------------------------------------------
// Kernel 4: exact fp32 rescore of 3 candidates + gather values[best]
// ---------------------------------------------------------------------------
__global__ void rescore_kernel(const float* __restrict__ Q, const float* __restrict__ K,
                               const float* __restrict__ V, float* __restrict__ out)
{
    const int row = blockIdx.x;
    const int tid = threadIdx.x;   // 256
    const int4 cd = g_cand[row];
    const float qi = g_qinv[row];

    float4 q = reinterpret_cast<const float4*>(Q + (size_t)row * D_)[tid];
    q.x *= qi; q.y *= qi; q.z *= qi; q.w *= qi;

    __shared__ float r[3][256];
    __shared__ int sbest;
    const int cands[3] = {cd.x, cd.y, cd.z};
#pragma unroll
    for (int c = 0; c < 3; c++) {
        const float ki = g_kinv[cands[c]];
        float4 k = reinterpret_cast<const float4*>(K + (size_t)cands[c] * D_)[tid];
        r[c][tid] = (q.x * k.x + q.y * k.y + q.z * k.z + q.w * k.w) * ki;
    }
    __syncthreads();
    for (int off = 128; off > 0; off >>= 1) {
        if (tid < off) {
            r[0][tid] += r[0][tid + off];
            r[1][tid] += r[1][tid + off];
            r[2][tid] += r[2][tid + off];
        }
        __syncthreads();
    }
    if (tid == 0) {
        float bv = r[0][0]; int bi = cands[0];
        for (int c = 1; c < 3; c++) {
            const float v = r[c][0];
            if (v > bv || (v == bv && cands[c] < bi)) { bv = v; bi = cands[c]; }
        }
        sbest = bi;
    }
    __syncthreads();
    reinterpret_cast<float4*>(out + (size_t)row * D_)[tid] =
        reinterpret_cast<const float4*>(V + (size_t)sbest * D_)[tid];
}

// ---------------------------------------------------------------------------
// Kernel 5: deterministic mean of row variances -> out[B*D]
// ---------------------------------------------------------------------------
__global__ void var_mean_kernel(float* __restrict__ out)
{
    __shared__ float sm[1024];
    const int tid = threadIdx.x;
    sm[tid] = g_var[tid] + g_var[tid + 1024] + g_var[tid + 2048] + g_var[tid + 3072];
    __syncthreads();
    for (int o = 512; o > 0; o >>= 1) {
        if (tid < o) sm[tid] += sm[tid + o];
        __syncthreads();
    }
    if (tid == 0) out[(size_t)B_ * D_] = sm[0] / (float)B_;
}

// ---------------------------------------------------------------------------
extern "C" void kernel_launch(void* const* d_in, const int* in_sizes, int n_in,
                              void* d_out, int out_size)
{
    const float* query  = (const float*)d_in[0];
    const float* keys   = (const float*)d_in[1];
    const float* values = (const float*)d_in[2];
    float* out = (float*)d_out;

    cudaFuncSetAttribute(sim_kernel, cudaFuncAttributeMaxDynamicSharedMemorySize, SMEM_DYN);

    prep_q_kernel<<<B_, 256>>>(query);
    prep_k_kernel<<<N_, 256>>>(keys);

    sim_kernel<<<dim3(NBLK, BBLK), 256, SMEM_DYN>>>();

    finalize_kernel<<<B_, 256>>>();
    rescore_kernel<<<B_, 256>>>(query, keys, values, out);
    var_mean_kernel<<<1, 1024>>>(out);
}